// round 13
// baseline (speedup 1.0000x reference)
#include <cuda_runtime.h>

#define T_TOK 2048
#define SDIM  1024
#define EDIM  1024
#define HID   150
#define MAXW  10

#define TMM    16             // tokens per MLP block
#define MLPW   640            // MLP compute threads (20 warps)
#define CPW    128            // copy threads (4 warps)
#define TOT    (MLPW + CPW)   // 768 threads = 6 warps/SMSP
#define KPAD   1032           // As row stride (floats)
#define HPAD   158            // h row stride (floats)
#define WROW   88             // w1 tile row stride (floats)
#define W2ROW  156            // w2 tile row stride (floats)
#define KC     64             // K-chunk (floats)
#define CHUNKS 16             // 1024 / 64
#define WTILE  (160 * WROW)   // floats per w1 buffer (14080)

#define SMEM_FLOATS (TMM*KPAD + 2*WTILE + 2*TMM*HPAD)   // ~199 KB

#define RB 8                  // span starts per pooled block

__device__ float g_attns[T_TOK];

#define CP16(dst_s, src_g) \
    asm volatile("cp.async.cg.shared.global [%0], [%1], 16;\n" :: "r"(dst_s), "l"(src_g))
#define CP8(dst_s, src_g) \
    asm volatile("cp.async.ca.shared.global [%0], [%1], 8;\n" :: "r"(dst_s), "l"(src_g))

// ---------------------------------------------------------------------------
// Kernel 1: fused 3-layer MLP + states-copy, WARP-SPECIALIZED.
// Threads 0..639: R12's proven MLP (5 warps/SMSP). Threads 640..767: 4 copy
// warps that stream the start/end-state output sections (40 stores/thread per
// chunk) inside the same barrier skeleton. Store backpressure stalls only the
// copy warps; compute warps keep their issue slots.
// ---------------------------------------------------------------------------
__global__ __launch_bounds__(TOT) void mlp_copy_kernel(
    const float* __restrict__ states,
    const float* __restrict__ w1, const float* __restrict__ b1,
    const float* __restrict__ w2, const float* __restrict__ b2,
    const float* __restrict__ w3, const float* __restrict__ b3,
    float* __restrict__ out)
{
    __shared__ __align__(16) float sm[SMEM_FLOATS];
    float* As  = sm;                    // [16][KPAD]
    float* wt  = As + TMM * KPAD;       // [2][WTILE] (later aliased by w2)
    float* h1s = wt + 2 * WTILE;        // [16][HPAD]
    float* h2s = h1s + TMM * HPAD;      // [16][HPAD]

    const int tid = threadIdx.x;
    const int t0  = blockIdx.x * TMM;
    float4* out4  = (float4*)out;

    const unsigned wt_s = (unsigned)__cvta_generic_to_shared(wt);

    // ---- stage w1 chunk 0 (all threads help) ----
    for (int u = tid; u < HID * 16; u += TOT) {
        const int j = u >> 4, seg = u & 15;
        const int rm = (j >> 1) + (j & 1) * 80;
        CP16(wt_s + (unsigned)(rm * WROW + seg * 4) * 4,
             w1 + (size_t)j * SDIM + seg * 4);
    }
    asm volatile("cp.async.commit_group;\n" ::: "memory");

    // ---- stage 16 token states ----
    for (int idx = tid; idx < TMM * (SDIM / 4); idx += TOT) {
        const int t = idx >> 8, k4 = idx & 255;
        const float4 v = ((const float4*)states)[(size_t)(t0 + t) * 256 + k4];
        *(float4*)&As[t * KPAD + k4 * 4] = v;
    }

    const bool is_mlp = (tid < MLPW);
    const int q  = tid & 3;
    const int kh = (tid >> 2) & 1;
    const int jp = tid >> 3;            // valid for MLP role
    const int j0 = 2 * jp;
    const int re = min(jp, 74);
    const int ro = 80 + re;
    const int ctid = tid - MLPW;        // 0..127 for copy role

    const float* A0 = As + (q + 0)  * KPAD;
    const float* A1 = As + (q + 4)  * KPAD;
    const float* A2 = As + (q + 8)  * KPAD;
    const float* A3 = As + (q + 12) * KPAD;

    float e0 = 0.f, e1 = 0.f, e2 = 0.f, e3 = 0.f;
    float o0 = 0.f, o1 = 0.f, o2 = 0.f, o3 = 0.f;

    for (int c = 0; c < CHUNKS; ++c) {
        if (c + 1 < CHUNKS) {
            const int nb = (c + 1) & 1;
            for (int u = tid; u < HID * 16; u += TOT) {
                const int j = u >> 4, seg = u & 15;
                const int rm = (j >> 1) + (j & 1) * 80;
                CP16(wt_s + (unsigned)(nb * WTILE + rm * WROW + seg * 4) * 4,
                     w1 + (size_t)j * SDIM + (c + 1) * KC + seg * 4);
            }
            asm volatile("cp.async.commit_group;\n" ::: "memory");
            asm volatile("cp.async.wait_group 1;\n" ::: "memory");
        } else {
            asm volatile("cp.async.wait_group 0;\n" ::: "memory");
        }
        __syncthreads();

        if (is_mlp) {
            const float* wb = wt + (c & 1) * WTILE;
            const float* we = wb + re * WROW + kh * 4;
            const float* wo = wb + ro * WROW + kh * 4;
            const float* B0 = A0 + c * KC + kh * 4;
            const float* B1 = A1 + c * KC + kh * 4;
            const float* B2 = A2 + c * KC + kh * 4;
            const float* B3 = A3 + c * KC + kh * 4;

            #pragma unroll
            for (int i = 0; i < 8; ++i) {
                const int o = i * 8;
                const float4 w_e = *(const float4*)(we + o);
                const float4 w_o = *(const float4*)(wo + o);
                const float4 a0 = *(const float4*)(B0 + o);
                const float4 a1 = *(const float4*)(B1 + o);
                const float4 a2 = *(const float4*)(B2 + o);
                const float4 a3 = *(const float4*)(B3 + o);
                e0 = fmaf(w_e.x, a0.x, e0); e0 = fmaf(w_e.y, a0.y, e0);
                e0 = fmaf(w_e.z, a0.z, e0); e0 = fmaf(w_e.w, a0.w, e0);
                e1 = fmaf(w_e.x, a1.x, e1); e1 = fmaf(w_e.y, a1.y, e1);
                e1 = fmaf(w_e.z, a1.z, e1); e1 = fmaf(w_e.w, a1.w, e1);
                e2 = fmaf(w_e.x, a2.x, e2); e2 = fmaf(w_e.y, a2.y, e2);
                e2 = fmaf(w_e.z, a2.z, e2); e2 = fmaf(w_e.w, a2.w, e2);
                e3 = fmaf(w_e.x, a3.x, e3); e3 = fmaf(w_e.y, a3.y, e3);
                e3 = fmaf(w_e.z, a3.z, e3); e3 = fmaf(w_e.w, a3.w, e3);
                o0 = fmaf(w_o.x, a0.x, o0); o0 = fmaf(w_o.y, a0.y, o0);
                o0 = fmaf(w_o.z, a0.z, o0); o0 = fmaf(w_o.w, a0.w, o0);
                o1 = fmaf(w_o.x, a1.x, o1); o1 = fmaf(w_o.y, a1.y, o1);
                o1 = fmaf(w_o.z, a1.z, o1); o1 = fmaf(w_o.w, a1.w, o1);
                o2 = fmaf(w_o.x, a2.x, o2); o2 = fmaf(w_o.y, a2.y, o2);
                o2 = fmaf(w_o.z, a2.z, o2); o2 = fmaf(w_o.w, a2.w, o2);
                o3 = fmaf(w_o.x, a3.x, o3); o3 = fmaf(w_o.y, a3.y, o3);
                o3 = fmaf(w_o.z, a3.z, o3); o3 = fmaf(w_o.w, a3.w, o3);
            }
        } else {
            // ---- copy warps: 40 items/thread/chunk; item = (sec, token, f4)
            #pragma unroll 8
            for (int it = 0; it < 40; ++it) {
                const int g    = c * 5120 + it * 128 + ctid;  // 0..81919
                const int f4   = g & 255;
                const int rest = g >> 8;                      // 0..319
                const int th   = rest & 15;
                const int sec  = rest >> 4;                   // 0..19
                const int wi   = (sec < 10) ? sec : sec - 10;
                const int r    = t0 + th;
                const float4 v = *(const float4*)&As[th * KPAD + f4 * 4];
                const int tri  = wi * (T_TOK + 1) - ((wi + 1) * wi) / 2;
                if (sec < 10) {
                    if (r + wi < T_TOK)
                        __stcs(&out4[(tri + r) * 768 + f4], v);
                } else {
                    if (r - wi >= 0)
                        __stcs(&out4[(tri + r - wi) * 768 + 256 + f4], v);
                }
            }
        }
        __syncthreads();
    }

    // ---- stage w2 ----
    for (int u = tid; u < HID * (HID / 2); u += TOT) {
        const int j = u / (HID / 2), s2 = u - j * (HID / 2);
        const int rm = (j >> 1) + (j & 1) * 76;
        CP8(wt_s + (unsigned)(rm * W2ROW + s2 * 2) * 4,
            w2 + (size_t)j * HID + s2 * 2);
    }
    asm volatile("cp.async.commit_group;\n" ::: "memory");

    // ---- write layer-1 partials (MLP role only) ----
    if (is_mlp && j0 < HID) {
        float* P = kh ? h2s : h1s;
        P[(q + 0)  * HPAD + j0]     = e0;
        P[(q + 4)  * HPAD + j0]     = e1;
        P[(q + 8)  * HPAD + j0]     = e2;
        P[(q + 12) * HPAD + j0]     = e3;
        P[(q + 0)  * HPAD + j0 + 1] = o0;
        P[(q + 4)  * HPAD + j0 + 1] = o1;
        P[(q + 8)  * HPAD + j0 + 1] = o2;
        P[(q + 12) * HPAD + j0 + 1] = o3;
    }
    __syncthreads();

    // ---- combine partials ----
    for (int idx = tid; idx < TMM * 160; idx += TOT) {
        const int t = idx / 160, j = idx - t * 160;
        if (j < HID)
            h1s[t * HPAD + j] = fmaxf(h1s[t * HPAD + j] + h2s[t * HPAD + j]
                                      + b1[j], 0.f);
    }
    asm volatile("cp.async.wait_group 0;\n" ::: "memory");
    __syncthreads();

    // ---------------- layer 2 (threads with j<150 produce; rest shadow) -----
    {
        const int j  = tid >> 2;                 // 0..191
        const int jc = min(j, HID - 1);
        const int rm = (jc >> 1) + (jc & 1) * 76;
        const float* wr = wt + rm * W2ROW;
        const float* B0 = h1s + (q + 0)  * HPAD;
        const float* B1 = h1s + (q + 4)  * HPAD;
        const float* B2 = h1s + (q + 8)  * HPAD;
        const float* B3 = h1s + (q + 12) * HPAD;

        float c0 = 0.f, c1 = 0.f, c2 = 0.f, c3 = 0.f;
        #pragma unroll 5
        for (int p = 0; p < HID / 2; ++p) {
            const float2 wv = *(const float2*)(wr + 2 * p);
            const float2 a0 = *(const float2*)(B0 + 2 * p);
            const float2 a1 = *(const float2*)(B1 + 2 * p);
            const float2 a2 = *(const float2*)(B2 + 2 * p);
            const float2 a3 = *(const float2*)(B3 + 2 * p);
            c0 = fmaf(wv.x, a0.x, c0); c0 = fmaf(wv.y, a0.y, c0);
            c1 = fmaf(wv.x, a1.x, c1); c1 = fmaf(wv.y, a1.y, c1);
            c2 = fmaf(wv.x, a2.x, c2); c2 = fmaf(wv.y, a2.y, c2);
            c3 = fmaf(wv.x, a3.x, c3); c3 = fmaf(wv.y, a3.y, c3);
        }
        __syncthreads();
        if (j < HID) {
            const float bb = b2[j];
            h2s[(q + 0)  * HPAD + j] = fmaxf(c0 + bb, 0.f);
            h2s[(q + 4)  * HPAD + j] = fmaxf(c1 + bb, 0.f);
            h2s[(q + 8)  * HPAD + j] = fmaxf(c2 + bb, 0.f);
            h2s[(q + 12) * HPAD + j] = fmaxf(c3 + bb, 0.f);
        }
    }
    __syncthreads();

    // ---------------- layer 3 ----------------
    {
        const int wrp  = tid >> 5;
        const int lane = tid & 31;
        if (wrp < TMM) {
            float acc = 0.f;
            #pragma unroll
            for (int i = 0; i < 5; ++i) {
                const int kk = lane + 32 * i;
                if (kk < HID) acc += w3[kk] * h2s[wrp * HPAD + kk];
            }
            #pragma unroll
            for (int off = 16; off; off >>= 1)
                acc += __shfl_xor_sync(0xffffffffu, acc, off);
            if (lane == 0) g_attns[t0 + wrp] = acc + b3[0];
        }
    }
}

// ---------------------------------------------------------------------------
// Kernel 2: pooled sections, 8 span-starts per block (grid 256).
// 17 embed rows prefetched once; 80 windows share them. Running-softmax
// numerator per start; writes only the pooled-embed third.
// ---------------------------------------------------------------------------
__global__ __launch_bounds__(256) void pooled_kernel(
    const float* __restrict__ embeds,
    float* __restrict__ out)
{
    const int r0  = blockIdx.x * RB;
    const int tid = threadIdx.x;
    const int nrows = min(RB + MAXW - 1, T_TOK - r0);    // up to 17

    __shared__ __align__(16) float se[RB + MAXW - 1][EDIM];  // 68 KB
    __shared__ float sc[RB + MAXW - 1];
    __shared__ float ws[RB][MAXW];
    __shared__ float invden[RB][MAXW];

    // prefetch embed rows (16B per thread per row)
    {
        unsigned sa = (unsigned)__cvta_generic_to_shared(&se[0][tid * 4]);
        const float4* src = (const float4*)embeds + (size_t)r0 * 256 + tid;
        #pragma unroll
        for (int i = 0; i < RB + MAXW - 1; i++) {
            if (i < nrows)
                asm volatile("cp.async.cg.shared.global [%0], [%1], 16;\n"
                             :: "r"(sa + i * (EDIM * 4)), "l"(src + i * 256));
        }
        asm volatile("cp.async.commit_group;\n" ::: "memory");
    }

    if (tid < nrows) sc[tid] = g_attns[r0 + tid];
    __syncthreads();

    // softmax prefixes: thread rr handles start r0+rr
    if (tid < RB) {
        const int nm = min(MAXW, T_TOK - (r0 + tid));
        float m = -1e30f;
        for (int i = 0; i < nm; i++) m = fmaxf(m, sc[tid + i]);
        float den = 0.f;
        for (int i = 0; i < nm; i++) {
            const float e = __expf(sc[tid + i] - m);
            ws[tid][i] = e;
            den += e;
            invden[tid][i] = 1.0f / den;
        }
    }
    asm volatile("cp.async.wait_group 0;\n" ::: "memory");
    __syncthreads();

    float4* out4 = (float4*)out;

    #pragma unroll
    for (int rr = 0; rr < RB; rr++) {
        const int r  = r0 + rr;
        const int nm = min(MAXW, T_TOK - r);
        float4 num = make_float4(0.f, 0.f, 0.f, 0.f);
        #pragma unroll
        for (int i = 0; i < MAXW; i++) {
            if (i < nm) {
                const float  wv = ws[rr][i];
                const float4 e  = ((const float4*)se[rr + i])[tid];
                num.x += wv * e.x; num.y += wv * e.y;
                num.z += wv * e.z; num.w += wv * e.w;

                const int row = i * (T_TOK + 1) - ((i + 1) * i) / 2 + r;
                const float id = invden[rr][i];
                __stcs(&out4[row * 768 + 512 + tid],
                       make_float4(num.x * id, num.y * id,
                                   num.z * id, num.w * id));
            }
        }
    }
}

// ---------------------------------------------------------------------------
extern "C" void kernel_launch(void* const* d_in, const int* in_sizes, int n_in,
                              void* d_out, int out_size) {
    const float* embeds = (const float*)d_in[0];
    const float* states = (const float*)d_in[1];
    const float* w1     = (const float*)d_in[2];
    const float* b1     = (const float*)d_in[3];
    const float* w2     = (const float*)d_in[4];
    const float* b2     = (const float*)d_in[5];
    const float* w3     = (const float*)d_in[6];
    const float* b3     = (const float*)d_in[7];
    float* out = (float*)d_out;

    mlp_copy_kernel<<<T_TOK / TMM, TOT>>>(states, w1, b1, w2, b2, w3, b3, out);
    pooled_kernel<<<T_TOK / RB, 256>>>(embeds, out);
}

// round 14
// speedup vs baseline: 1.1756x; 1.1756x over previous
#include <cuda_runtime.h>

#define T_TOK 2048
#define SDIM  1024
#define EDIM  1024
#define HID   150
#define MAXW  10

#define TMM    16             // tokens per MLP block
#define MLPT   640            // MLP threads (20 warps = 5/SMSP)
#define KPAD   1032           // As row stride (floats)
#define HPAD   158            // h row stride (floats)
#define WROW   88             // w1 tile row stride (floats)
#define W2ROW  156            // w2 tile row stride (floats)
#define KC     64             // K-chunk (floats)
#define CHUNKS 16             // 1024 / 64
#define WTILE  (160 * WROW)   // floats per w1 buffer (14080)

#define SMEM_FLOATS (TMM*KPAD + 2*WTILE + 2*TMM*HPAD)   // ~199 KB

#define RB 8                  // span starts per pooled block

__device__ float g_attns[T_TOK];

#define CP16(dst_s, src_g) \
    asm volatile("cp.async.cg.shared.global [%0], [%1], 16;\n" :: "r"(dst_s), "l"(src_g))
#define CP8(dst_s, src_g) \
    asm volatile("cp.async.ca.shared.global [%0], [%1], 8;\n" :: "r"(dst_s), "l"(src_g))

// ---------------------------------------------------------------------------
// Kernel 1 (R12-proven): fused 3-layer MLP + states-copy, INTERLEAVED.
// All 640 threads compute the MLP; each also issues 8 copy stores per chunk
// (start/end-state output sections, 167 MB total) so store issue pressure is
// spread across 20 warps instead of being a narrow role's critical path.
// ---------------------------------------------------------------------------
__global__ __launch_bounds__(MLPT) void mlp_copy_kernel(
    const float* __restrict__ states,
    const float* __restrict__ w1, const float* __restrict__ b1,
    const float* __restrict__ w2, const float* __restrict__ b2,
    const float* __restrict__ w3, const float* __restrict__ b3,
    float* __restrict__ out)
{
    __shared__ __align__(16) float sm[SMEM_FLOATS];
    float* As  = sm;                    // [16][KPAD]
    float* wt  = As + TMM * KPAD;       // [2][WTILE] (later aliased by w2)
    float* h1s = wt + 2 * WTILE;        // [16][HPAD]
    float* h2s = h1s + TMM * HPAD;      // [16][HPAD]

    const int tid = threadIdx.x;
    const int t0  = blockIdx.x * TMM;
    float4* out4  = (float4*)out;

    const unsigned wt_s = (unsigned)__cvta_generic_to_shared(wt);

    // ---- stage w1 chunk 0 ----
    for (int u = tid; u < HID * 16; u += MLPT) {
        const int j = u >> 4, seg = u & 15;
        const int rm = (j >> 1) + (j & 1) * 80;
        CP16(wt_s + (unsigned)(rm * WROW + seg * 4) * 4,
             w1 + (size_t)j * SDIM + seg * 4);
    }
    asm volatile("cp.async.commit_group;\n" ::: "memory");

    // ---- stage 16 token states ----
    for (int idx = tid; idx < TMM * (SDIM / 4); idx += MLPT) {
        const int t = idx >> 8, k4 = idx & 255;
        const float4 v = ((const float4*)states)[(size_t)(t0 + t) * 256 + k4];
        *(float4*)&As[t * KPAD + k4 * 4] = v;
    }

    const int q  = tid & 3;
    const int kh = (tid >> 2) & 1;
    const int jp = tid >> 3;
    const int j0 = 2 * jp;
    const int re = min(jp, 74);
    const int ro = 80 + re;

    const float* A0 = As + (q + 0)  * KPAD;
    const float* A1 = As + (q + 4)  * KPAD;
    const float* A2 = As + (q + 8)  * KPAD;
    const float* A3 = As + (q + 12) * KPAD;

    float e0 = 0.f, e1 = 0.f, e2 = 0.f, e3 = 0.f;
    float o0 = 0.f, o1 = 0.f, o2 = 0.f, o3 = 0.f;

    for (int c = 0; c < CHUNKS; ++c) {
        if (c + 1 < CHUNKS) {
            const int nb = (c + 1) & 1;
            for (int u = tid; u < HID * 16; u += MLPT) {
                const int j = u >> 4, seg = u & 15;
                const int rm = (j >> 1) + (j & 1) * 80;
                CP16(wt_s + (unsigned)(nb * WTILE + rm * WROW + seg * 4) * 4,
                     w1 + (size_t)j * SDIM + (c + 1) * KC + seg * 4);
            }
            asm volatile("cp.async.commit_group;\n" ::: "memory");
            asm volatile("cp.async.wait_group 1;\n" ::: "memory");
        } else {
            asm volatile("cp.async.wait_group 0;\n" ::: "memory");
        }
        __syncthreads();

        const float* wb = wt + (c & 1) * WTILE;
        const float* we = wb + re * WROW + kh * 4;
        const float* wo = wb + ro * WROW + kh * 4;
        const float* B0 = A0 + c * KC + kh * 4;
        const float* B1 = A1 + c * KC + kh * 4;
        const float* B2 = A2 + c * KC + kh * 4;
        const float* B3 = A3 + c * KC + kh * 4;

        #pragma unroll
        for (int i = 0; i < 8; ++i) {
            const int o = i * 8;
            const float4 w_e = *(const float4*)(we + o);
            const float4 w_o = *(const float4*)(wo + o);
            const float4 a0 = *(const float4*)(B0 + o);
            const float4 a1 = *(const float4*)(B1 + o);
            const float4 a2 = *(const float4*)(B2 + o);
            const float4 a3 = *(const float4*)(B3 + o);
            e0 = fmaf(w_e.x, a0.x, e0); e0 = fmaf(w_e.y, a0.y, e0);
            e0 = fmaf(w_e.z, a0.z, e0); e0 = fmaf(w_e.w, a0.w, e0);
            e1 = fmaf(w_e.x, a1.x, e1); e1 = fmaf(w_e.y, a1.y, e1);
            e1 = fmaf(w_e.z, a1.z, e1); e1 = fmaf(w_e.w, a1.w, e1);
            e2 = fmaf(w_e.x, a2.x, e2); e2 = fmaf(w_e.y, a2.y, e2);
            e2 = fmaf(w_e.z, a2.z, e2); e2 = fmaf(w_e.w, a2.w, e2);
            e3 = fmaf(w_e.x, a3.x, e3); e3 = fmaf(w_e.y, a3.y, e3);
            e3 = fmaf(w_e.z, a3.z, e3); e3 = fmaf(w_e.w, a3.w, e3);
            o0 = fmaf(w_o.x, a0.x, o0); o0 = fmaf(w_o.y, a0.y, o0);
            o0 = fmaf(w_o.z, a0.z, o0); o0 = fmaf(w_o.w, a0.w, o0);
            o1 = fmaf(w_o.x, a1.x, o1); o1 = fmaf(w_o.y, a1.y, o1);
            o1 = fmaf(w_o.z, a1.z, o1); o1 = fmaf(w_o.w, a1.w, o1);
            o2 = fmaf(w_o.x, a2.x, o2); o2 = fmaf(w_o.y, a2.y, o2);
            o2 = fmaf(w_o.z, a2.z, o2); o2 = fmaf(w_o.w, a2.w, o2);
            o3 = fmaf(w_o.x, a3.x, o3); o3 = fmaf(w_o.y, a3.y, o3);
            o3 = fmaf(w_o.z, a3.z, o3); o3 = fmaf(w_o.w, a3.w, o3);
        }

        // ---- interleaved copy stores: 8 items/thread/chunk ----
        #pragma unroll
        for (int it = 0; it < 8; ++it) {
            const int g    = (c * 8 + it) * MLPT + tid;   // 0..81919
            const int f4   = g & 255;
            const int rest = g >> 8;                      // 0..319
            const int th   = rest & 15;
            const int sec  = rest >> 4;                   // 0..19
            const int wi   = (sec < 10) ? sec : sec - 10;
            const int r    = t0 + th;
            const float4 v = *(const float4*)&As[th * KPAD + f4 * 4];
            const int tri  = wi * (T_TOK + 1) - ((wi + 1) * wi) / 2;
            if (sec < 10) {
                if (r + wi < T_TOK)
                    __stcs(&out4[(tri + r) * 768 + f4], v);
            } else {
                if (r - wi >= 0)
                    __stcs(&out4[(tri + r - wi) * 768 + 256 + f4], v);
            }
        }
        __syncthreads();
    }

    // ---- stage w2 ----
    for (int u = tid; u < HID * (HID / 2); u += MLPT) {
        const int j = u / (HID / 2), s2 = u - j * (HID / 2);
        const int rm = (j >> 1) + (j & 1) * 76;
        CP8(wt_s + (unsigned)(rm * W2ROW + s2 * 2) * 4,
            w2 + (size_t)j * HID + s2 * 2);
    }
    asm volatile("cp.async.commit_group;\n" ::: "memory");

    // ---- write layer-1 partials ----
    if (j0 < HID) {
        float* P = kh ? h2s : h1s;
        P[(q + 0)  * HPAD + j0]     = e0;
        P[(q + 4)  * HPAD + j0]     = e1;
        P[(q + 8)  * HPAD + j0]     = e2;
        P[(q + 12) * HPAD + j0]     = e3;
        P[(q + 0)  * HPAD + j0 + 1] = o0;
        P[(q + 4)  * HPAD + j0 + 1] = o1;
        P[(q + 8)  * HPAD + j0 + 1] = o2;
        P[(q + 12) * HPAD + j0 + 1] = o3;
    }
    __syncthreads();

    // ---- combine partials: h1 = relu(p_even + p_odd + b1) ----
    for (int idx = tid; idx < TMM * 160; idx += MLPT) {
        const int t = idx / 160, j = idx - t * 160;
        if (j < HID)
            h1s[t * HPAD + j] = fmaxf(h1s[t * HPAD + j] + h2s[t * HPAD + j]
                                      + b1[j], 0.f);
    }
    asm volatile("cp.async.wait_group 0;\n" ::: "memory");
    __syncthreads();

    // ---------------- layer 2 ----------------
    {
        const int j  = tid >> 2;
        const int jc = min(j, HID - 1);
        const int rm = (jc >> 1) + (jc & 1) * 76;
        const float* wr = wt + rm * W2ROW;
        const float* B0 = h1s + (q + 0)  * HPAD;
        const float* B1 = h1s + (q + 4)  * HPAD;
        const float* B2 = h1s + (q + 8)  * HPAD;
        const float* B3 = h1s + (q + 12) * HPAD;

        float c0 = 0.f, c1 = 0.f, c2 = 0.f, c3 = 0.f;
        #pragma unroll 5
        for (int p = 0; p < HID / 2; ++p) {
            const float2 wv = *(const float2*)(wr + 2 * p);
            const float2 a0 = *(const float2*)(B0 + 2 * p);
            const float2 a1 = *(const float2*)(B1 + 2 * p);
            const float2 a2 = *(const float2*)(B2 + 2 * p);
            const float2 a3 = *(const float2*)(B3 + 2 * p);
            c0 = fmaf(wv.x, a0.x, c0); c0 = fmaf(wv.y, a0.y, c0);
            c1 = fmaf(wv.x, a1.x, c1); c1 = fmaf(wv.y, a1.y, c1);
            c2 = fmaf(wv.x, a2.x, c2); c2 = fmaf(wv.y, a2.y, c2);
            c3 = fmaf(wv.x, a3.x, c3); c3 = fmaf(wv.y, a3.y, c3);
        }
        __syncthreads();
        if (j < HID) {
            const float bb = b2[j];
            h2s[(q + 0)  * HPAD + j] = fmaxf(c0 + bb, 0.f);
            h2s[(q + 4)  * HPAD + j] = fmaxf(c1 + bb, 0.f);
            h2s[(q + 8)  * HPAD + j] = fmaxf(c2 + bb, 0.f);
            h2s[(q + 12) * HPAD + j] = fmaxf(c3 + bb, 0.f);
        }
    }
    __syncthreads();

    // ---------------- layer 3 ----------------
    {
        const int wrp  = tid >> 5;
        const int lane = tid & 31;
        if (wrp < TMM) {
            float acc = 0.f;
            #pragma unroll
            for (int i = 0; i < 5; ++i) {
                const int kk = lane + 32 * i;
                if (kk < HID) acc += w3[kk] * h2s[wrp * HPAD + kk];
            }
            #pragma unroll
            for (int off = 16; off; off >>= 1)
                acc += __shfl_xor_sync(0xffffffffu, acc, off);
            if (lane == 0) g_attns[t0 + wrp] = acc + b3[0];
        }
    }
}

// ---------------------------------------------------------------------------
// Kernel 2 (R13-proven): pooled sections, 8 span-starts per block (grid 256).
// 17 embed rows prefetched once; 80 windows share them.
// ---------------------------------------------------------------------------
__global__ __launch_bounds__(256) void pooled_kernel(
    const float* __restrict__ embeds,
    float* __restrict__ out)
{
    const int r0  = blockIdx.x * RB;
    const int tid = threadIdx.x;
    const int nrows = min(RB + MAXW - 1, T_TOK - r0);    // up to 17

    __shared__ __align__(16) float se[RB + MAXW - 1][EDIM];  // 68 KB
    __shared__ float sc[RB + MAXW - 1];
    __shared__ float ws[RB][MAXW];
    __shared__ float invden[RB][MAXW];

    {
        unsigned sa = (unsigned)__cvta_generic_to_shared(&se[0][tid * 4]);
        const float4* src = (const float4*)embeds + (size_t)r0 * 256 + tid;
        #pragma unroll
        for (int i = 0; i < RB + MAXW - 1; i++) {
            if (i < nrows)
                asm volatile("cp.async.cg.shared.global [%0], [%1], 16;\n"
                             :: "r"(sa + i * (EDIM * 4)), "l"(src + i * 256));
        }
        asm volatile("cp.async.commit_group;\n" ::: "memory");
    }

    if (tid < nrows) sc[tid] = g_attns[r0 + tid];
    __syncthreads();

    if (tid < RB) {
        const int nm = min(MAXW, T_TOK - (r0 + tid));
        float m = -1e30f;
        for (int i = 0; i < nm; i++) m = fmaxf(m, sc[tid + i]);
        float den = 0.f;
        for (int i = 0; i < nm; i++) {
            const float e = __expf(sc[tid + i] - m);
            ws[tid][i] = e;
            den += e;
            invden[tid][i] = 1.0f / den;
        }
    }
    asm volatile("cp.async.wait_group 0;\n" ::: "memory");
    __syncthreads();

    float4* out4 = (float4*)out;

    #pragma unroll
    for (int rr = 0; rr < RB; rr++) {
        const int r  = r0 + rr;
        const int nm = min(MAXW, T_TOK - r);
        float4 num = make_float4(0.f, 0.f, 0.f, 0.f);
        #pragma unroll
        for (int i = 0; i < MAXW; i++) {
            if (i < nm) {
                const float  wv = ws[rr][i];
                const float4 e  = ((const float4*)se[rr + i])[tid];
                num.x += wv * e.x; num.y += wv * e.y;
                num.z += wv * e.z; num.w += wv * e.w;

                const int row = i * (T_TOK + 1) - ((i + 1) * i) / 2 + r;
                const float id = invden[rr][i];
                __stcs(&out4[row * 768 + 512 + tid],
                       make_float4(num.x * id, num.y * id,
                                   num.z * id, num.w * id));
            }
        }
    }
}

// ---------------------------------------------------------------------------
extern "C" void kernel_launch(void* const* d_in, const int* in_sizes, int n_in,
                              void* d_out, int out_size) {
    const float* embeds = (const float*)d_in[0];
    const float* states = (const float*)d_in[1];
    const float* w1     = (const float*)d_in[2];
    const float* b1     = (const float*)d_in[3];
    const float* w2     = (const float*)d_in[4];
    const float* b2     = (const float*)d_in[5];
    const float* w3     = (const float*)d_in[6];
    const float* b3     = (const float*)d_in[7];
    float* out = (float*)d_out;

    mlp_copy_kernel<<<T_TOK / TMM, MLPT>>>(states, w1, b1, w2, b2, w3, b3, out);
    pooled_kernel<<<T_TOK / RB, 256>>>(embeds, out);
}

// round 15
// speedup vs baseline: 1.1865x; 1.0093x over previous
#include <cuda_runtime.h>

#define T_TOK 2048
#define SDIM  1024
#define EDIM  1024
#define HID   150
#define MAXW  10

#define TMM    16             // tokens per block
#define MLPT   640            // threads (20 warps = 5/SMSP)
#define KPAD   1032           // As row stride (floats)
#define HPAD   158            // h row stride (floats)
#define WROW   88             // w1 tile row stride (floats)
#define W2ROW  156            // w2 tile row stride (floats)
#define KC     64             // K-chunk (floats)
#define CHUNKS 16             // 1024 / 64
#define WTILE  (160 * WROW)   // floats per w1 buffer (14080)
#define NBLK   (T_TOK / TMM)  // 128 blocks (all co-resident: 1/SM, 148 SMs)

#define SMEM_FLOATS (TMM*KPAD + 2*WTILE + 2*TMM*HPAD)   // 45888 -> ~199 KB

// phase-B smem carve-out (aliases As+wt, free after layer 2):
#define SE_OFF   0          // 25 embed rows x 1024 floats = 25600
#define SCB_OFF  25600      // 25 scores
#define WS_OFF   25632      // 16 starts x 10 widths
#define IDN_OFF  25792      // 16 x 10

__device__ float g_attns[T_TOK];
__device__ int   g_done[NBLK];

#define CP16(dst_s, src_g) \
    asm volatile("cp.async.cg.shared.global [%0], [%1], 16;\n" :: "r"(dst_s), "l"(src_g))
#define CP8(dst_s, src_g) \
    asm volatile("cp.async.ca.shared.global [%0], [%1], 8;\n" :: "r"(dst_s), "l"(src_g))

// ---------------------------------------------------------------------------
// Prologue: reset inter-block flags (runs each graph replay before main).
// ---------------------------------------------------------------------------
__global__ void reset_flags_kernel() {
    g_done[threadIdx.x] = 0;
}

// ---------------------------------------------------------------------------
// Fused kernel. Phase A (R12/R14-proven): MLP + interleaved states-copy.
// Publish g_attns + release flag. Phase B (R13-proven logic): running-softmax
// pooled sections for this block's 16 starts, after acquiring block b+1's
// scores. Embed prefetch overlaps the flag wait.
// ---------------------------------------------------------------------------
__global__ __launch_bounds__(MLPT) void fused_kernel(
    const float* __restrict__ embeds,
    const float* __restrict__ states,
    const float* __restrict__ w1, const float* __restrict__ b1,
    const float* __restrict__ w2, const float* __restrict__ b2,
    const float* __restrict__ w3, const float* __restrict__ b3,
    float* __restrict__ out)
{
    __shared__ __align__(16) float sm[SMEM_FLOATS];
    float* As  = sm;                    // [16][KPAD]
    float* wt  = As + TMM * KPAD;       // [2][WTILE] (aliased by w2, then se)
    float* h1s = wt + 2 * WTILE;        // [16][HPAD]
    float* h2s = h1s + TMM * HPAD;      // [16][HPAD]

    const int tid = threadIdx.x;
    const int bid = blockIdx.x;
    const int t0  = bid * TMM;
    float4* out4  = (float4*)out;

    const unsigned wt_s = (unsigned)__cvta_generic_to_shared(wt);
    const unsigned sm_s = (unsigned)__cvta_generic_to_shared(sm);

    // ---- stage w1 chunk 0 ----
    for (int u = tid; u < HID * 16; u += MLPT) {
        const int j = u >> 4, seg = u & 15;
        const int rm = (j >> 1) + (j & 1) * 80;
        CP16(wt_s + (unsigned)(rm * WROW + seg * 4) * 4,
             w1 + (size_t)j * SDIM + seg * 4);
    }
    asm volatile("cp.async.commit_group;\n" ::: "memory");

    // ---- stage 16 token states ----
    for (int idx = tid; idx < TMM * (SDIM / 4); idx += MLPT) {
        const int t = idx >> 8, k4 = idx & 255;
        const float4 v = ((const float4*)states)[(size_t)(t0 + t) * 256 + k4];
        *(float4*)&As[t * KPAD + k4 * 4] = v;
    }

    const int q  = tid & 3;
    const int kh = (tid >> 2) & 1;
    const int jp = tid >> 3;
    const int j0 = 2 * jp;
    const int re = min(jp, 74);
    const int ro = 80 + re;

    const float* A0 = As + (q + 0)  * KPAD;
    const float* A1 = As + (q + 4)  * KPAD;
    const float* A2 = As + (q + 8)  * KPAD;
    const float* A3 = As + (q + 12) * KPAD;

    float e0 = 0.f, e1 = 0.f, e2 = 0.f, e3 = 0.f;
    float o0 = 0.f, o1 = 0.f, o2 = 0.f, o3 = 0.f;

    for (int c = 0; c < CHUNKS; ++c) {
        if (c + 1 < CHUNKS) {
            const int nb = (c + 1) & 1;
            for (int u = tid; u < HID * 16; u += MLPT) {
                const int j = u >> 4, seg = u & 15;
                const int rm = (j >> 1) + (j & 1) * 80;
                CP16(wt_s + (unsigned)(nb * WTILE + rm * WROW + seg * 4) * 4,
                     w1 + (size_t)j * SDIM + (c + 1) * KC + seg * 4);
            }
            asm volatile("cp.async.commit_group;\n" ::: "memory");
            asm volatile("cp.async.wait_group 1;\n" ::: "memory");
        } else {
            asm volatile("cp.async.wait_group 0;\n" ::: "memory");
        }
        __syncthreads();

        const float* wb = wt + (c & 1) * WTILE;
        const float* we = wb + re * WROW + kh * 4;
        const float* wo = wb + ro * WROW + kh * 4;
        const float* B0 = A0 + c * KC + kh * 4;
        const float* B1 = A1 + c * KC + kh * 4;
        const float* B2 = A2 + c * KC + kh * 4;
        const float* B3 = A3 + c * KC + kh * 4;

        #pragma unroll
        for (int i = 0; i < 8; ++i) {
            const int o = i * 8;
            const float4 w_e = *(const float4*)(we + o);
            const float4 w_o = *(const float4*)(wo + o);
            const float4 a0 = *(const float4*)(B0 + o);
            const float4 a1 = *(const float4*)(B1 + o);
            const float4 a2 = *(const float4*)(B2 + o);
            const float4 a3 = *(const float4*)(B3 + o);
            e0 = fmaf(w_e.x, a0.x, e0); e0 = fmaf(w_e.y, a0.y, e0);
            e0 = fmaf(w_e.z, a0.z, e0); e0 = fmaf(w_e.w, a0.w, e0);
            e1 = fmaf(w_e.x, a1.x, e1); e1 = fmaf(w_e.y, a1.y, e1);
            e1 = fmaf(w_e.z, a1.z, e1); e1 = fmaf(w_e.w, a1.w, e1);
            e2 = fmaf(w_e.x, a2.x, e2); e2 = fmaf(w_e.y, a2.y, e2);
            e2 = fmaf(w_e.z, a2.z, e2); e2 = fmaf(w_e.w, a2.w, e2);
            e3 = fmaf(w_e.x, a3.x, e3); e3 = fmaf(w_e.y, a3.y, e3);
            e3 = fmaf(w_e.z, a3.z, e3); e3 = fmaf(w_e.w, a3.w, e3);
            o0 = fmaf(w_o.x, a0.x, o0); o0 = fmaf(w_o.y, a0.y, o0);
            o0 = fmaf(w_o.z, a0.z, o0); o0 = fmaf(w_o.w, a0.w, o0);
            o1 = fmaf(w_o.x, a1.x, o1); o1 = fmaf(w_o.y, a1.y, o1);
            o1 = fmaf(w_o.z, a1.z, o1); o1 = fmaf(w_o.w, a1.w, o1);
            o2 = fmaf(w_o.x, a2.x, o2); o2 = fmaf(w_o.y, a2.y, o2);
            o2 = fmaf(w_o.z, a2.z, o2); o2 = fmaf(w_o.w, a2.w, o2);
            o3 = fmaf(w_o.x, a3.x, o3); o3 = fmaf(w_o.y, a3.y, o3);
            o3 = fmaf(w_o.z, a3.z, o3); o3 = fmaf(w_o.w, a3.w, o3);
        }

        // ---- interleaved copy stores: 8 items/thread/chunk ----
        #pragma unroll
        for (int it = 0; it < 8; ++it) {
            const int g    = (c * 8 + it) * MLPT + tid;   // 0..81919
            const int f4   = g & 255;
            const int rest = g >> 8;                      // 0..319
            const int th   = rest & 15;
            const int sec  = rest >> 4;                   // 0..19
            const int wi   = (sec < 10) ? sec : sec - 10;
            const int r    = t0 + th;
            const float4 v = *(const float4*)&As[th * KPAD + f4 * 4];
            const int tri  = wi * (T_TOK + 1) - ((wi + 1) * wi) / 2;
            if (sec < 10) {
                if (r + wi < T_TOK)
                    __stcs(&out4[(tri + r) * 768 + f4], v);
            } else {
                if (r - wi >= 0)
                    __stcs(&out4[(tri + r - wi) * 768 + 256 + f4], v);
            }
        }
        __syncthreads();
    }

    // ---- stage w2 ----
    for (int u = tid; u < HID * (HID / 2); u += MLPT) {
        const int j = u / (HID / 2), s2 = u - j * (HID / 2);
        const int rm = (j >> 1) + (j & 1) * 76;
        CP8(wt_s + (unsigned)(rm * W2ROW + s2 * 2) * 4,
            w2 + (size_t)j * HID + s2 * 2);
    }
    asm volatile("cp.async.commit_group;\n" ::: "memory");

    // ---- write layer-1 partials ----
    if (j0 < HID) {
        float* P = kh ? h2s : h1s;
        P[(q + 0)  * HPAD + j0]     = e0;
        P[(q + 4)  * HPAD + j0]     = e1;
        P[(q + 8)  * HPAD + j0]     = e2;
        P[(q + 12) * HPAD + j0]     = e3;
        P[(q + 0)  * HPAD + j0 + 1] = o0;
        P[(q + 4)  * HPAD + j0 + 1] = o1;
        P[(q + 8)  * HPAD + j0 + 1] = o2;
        P[(q + 12) * HPAD + j0 + 1] = o3;
    }
    __syncthreads();

    // ---- combine partials: h1 = relu(p_even + p_odd + b1) ----
    for (int idx = tid; idx < TMM * 160; idx += MLPT) {
        const int t = idx / 160, j = idx - t * 160;
        if (j < HID)
            h1s[t * HPAD + j] = fmaxf(h1s[t * HPAD + j] + h2s[t * HPAD + j]
                                      + b1[j], 0.f);
    }
    asm volatile("cp.async.wait_group 0;\n" ::: "memory");
    __syncthreads();

    // ---------------- layer 2 ----------------
    {
        const int j  = tid >> 2;
        const int jc = min(j, HID - 1);
        const int rm = (jc >> 1) + (jc & 1) * 76;
        const float* wr = wt + rm * W2ROW;
        const float* B0 = h1s + (q + 0)  * HPAD;
        const float* B1 = h1s + (q + 4)  * HPAD;
        const float* B2 = h1s + (q + 8)  * HPAD;
        const float* B3 = h1s + (q + 12) * HPAD;

        float c0 = 0.f, c1 = 0.f, c2 = 0.f, c3 = 0.f;
        #pragma unroll 5
        for (int p = 0; p < HID / 2; ++p) {
            const float2 wv = *(const float2*)(wr + 2 * p);
            const float2 a0 = *(const float2*)(B0 + 2 * p);
            const float2 a1 = *(const float2*)(B1 + 2 * p);
            const float2 a2 = *(const float2*)(B2 + 2 * p);
            const float2 a3 = *(const float2*)(B3 + 2 * p);
            c0 = fmaf(wv.x, a0.x, c0); c0 = fmaf(wv.y, a0.y, c0);
            c1 = fmaf(wv.x, a1.x, c1); c1 = fmaf(wv.y, a1.y, c1);
            c2 = fmaf(wv.x, a2.x, c2); c2 = fmaf(wv.y, a2.y, c2);
            c3 = fmaf(wv.x, a3.x, c3); c3 = fmaf(wv.y, a3.y, c3);
        }
        __syncthreads();
        if (j < HID) {
            const float bb = b2[j];
            h2s[(q + 0)  * HPAD + j] = fmaxf(c0 + bb, 0.f);
            h2s[(q + 4)  * HPAD + j] = fmaxf(c1 + bb, 0.f);
            h2s[(q + 8)  * HPAD + j] = fmaxf(c2 + bb, 0.f);
            h2s[(q + 12) * HPAD + j] = fmaxf(c3 + bb, 0.f);
        }
    }
    __syncthreads();

    // ---- phase-B embed prefetch (As/wt regions are dead now except h2s) ----
    {
        const int nrows = min(TMM + MAXW - 1, T_TOK - t0);   // up to 25
        const int f4 = tid & 255, rr = tid >> 8;             // 2.5 rows/pass
        for (int i = rr; i < nrows; i += 2) {                // rows 0,2,4.. & 1,3,..
            if (tid < 512)
                CP16(sm_s + (unsigned)(SE_OFF + i * EDIM + f4 * 4) * 4,
                     (const float4*)embeds + (size_t)(t0 + i) * 256 + f4);
        }
        asm volatile("cp.async.commit_group;\n" ::: "memory");
    }

    // ---------------- layer 3 + score publish ----------------
    {
        const int wrp  = tid >> 5;
        const int lane = tid & 31;
        if (wrp < TMM) {
            float acc = 0.f;
            #pragma unroll
            for (int i = 0; i < 5; ++i) {
                const int kk = lane + 32 * i;
                if (kk < HID) acc += w3[kk] * h2s[wrp * HPAD + kk];
            }
            #pragma unroll
            for (int off = 16; off; off >>= 1)
                acc += __shfl_xor_sync(0xffffffffu, acc, off);
            if (lane == 0) {
                const float v = acc + b3[0];
                g_attns[t0 + wrp] = v;
                sm[SCB_OFF + wrp] = v;        // own scores to smem
            }
        }
    }
    __threadfence();
    __syncthreads();
    if (tid == 0) atomicExch(&g_done[bid], 1);

    // ---- acquire neighbor's scores ----
    if (tid == 0 && bid + 1 < NBLK) {
        while (atomicAdd(&g_done[bid + 1], 0) == 0) { }
    }
    __threadfence();
    __syncthreads();

    if (tid < MAXW - 1 && t0 + TMM + tid < T_TOK)
        sm[SCB_OFF + TMM + tid] = g_attns[t0 + TMM + tid];
    __syncthreads();

    // ---- softmax prefixes for 16 starts ----
    if (tid < TMM) {
        const int r  = t0 + tid;
        const int nm = min(MAXW, T_TOK - r);
        float m = -1e30f;
        for (int i = 0; i < nm; i++) m = fmaxf(m, sm[SCB_OFF + tid + i]);
        float den = 0.f;
        for (int i = 0; i < nm; i++) {
            const float e = __expf(sm[SCB_OFF + tid + i] - m);
            sm[WS_OFF + tid * MAXW + i] = e;
            den += e;
            sm[IDN_OFF + tid * MAXW + i] = 1.0f / den;
        }
    }
    asm volatile("cp.async.wait_group 0;\n" ::: "memory");
    __syncthreads();

    // ---- pooled compute + stores: 512 threads, 8 starts each group --------
    if (tid < 512) {
        const int grp = tid >> 8;          // 0..1
        const int f4  = tid & 255;
        #pragma unroll
        for (int rr8 = 0; rr8 < 8; rr8++) {
            const int rr = grp * 8 + rr8;
            const int r  = t0 + rr;
            const int nm = min(MAXW, T_TOK - r);
            float4 num = make_float4(0.f, 0.f, 0.f, 0.f);
            #pragma unroll
            for (int i = 0; i < MAXW; i++) {
                if (i < nm) {
                    const float  wv = sm[WS_OFF + rr * MAXW + i];
                    const float4 e  =
                        *(const float4*)&sm[SE_OFF + (rr + i) * EDIM + f4 * 4];
                    num.x += wv * e.x; num.y += wv * e.y;
                    num.z += wv * e.z; num.w += wv * e.w;

                    const int row = i * (T_TOK + 1) - ((i + 1) * i) / 2 + r;
                    const float id = sm[IDN_OFF + rr * MAXW + i];
                    __stcs(&out4[row * 768 + 512 + f4],
                           make_float4(num.x * id, num.y * id,
                                       num.z * id, num.w * id));
                }
            }
        }
    }
}

// ---------------------------------------------------------------------------
extern "C" void kernel_launch(void* const* d_in, const int* in_sizes, int n_in,
                              void* d_out, int out_size) {
    const float* embeds = (const float*)d_in[0];
    const float* states = (const float*)d_in[1];
    const float* w1     = (const float*)d_in[2];
    const float* b1     = (const float*)d_in[3];
    const float* w2     = (const float*)d_in[4];
    const float* b2     = (const float*)d_in[5];
    const float* w3     = (const float*)d_in[6];
    const float* b3     = (const float*)d_in[7];
    float* out = (float*)d_out;

    reset_flags_kernel<<<1, NBLK>>>();
    fused_kernel<<<NBLK, MLPT>>>(embeds, states, w1, b1, w2, b2, w3, b3, out);
}

// round 16
// speedup vs baseline: 1.2269x; 1.0340x over previous
#include <cuda_runtime.h>

#define T_TOK 2048
#define SDIM  1024
#define EDIM  1024
#define HID   150
#define MAXW  10

#define TMM    16             // tokens per block
#define MLPT   640            // threads (20 warps = 5/SMSP)
#define KPAD   1032           // As row stride (floats)
#define HPAD   158            // h row stride (floats)
#define WROW   88             // w1 tile row stride (floats)
#define W2ROW  156            // w2 tile row stride (floats)
#define KC     64             // K-chunk (floats)
#define CHUNKS 16             // 1024 / 64
#define WTILE  (160 * WROW)   // floats per w1 buffer (14080)
#define NBLK   (T_TOK / TMM)  // 128 blocks (all co-resident: 1/SM, 148 SMs)

#define SMEM_FLOATS (TMM*KPAD + 2*WTILE + 2*TMM*HPAD)   // 45888 -> ~199 KB

// phase-B smem carve-out (aliases As+wt, free after layer 2):
#define SE_OFF   0          // 25 embed rows x 1024 floats = 25600
#define SCB_OFF  25600      // 25 scores
#define WS_OFF   25632      // 16 starts x 10 widths
#define IDN_OFF  25792      // 16 x 10

__device__ float g_attns[T_TOK];
__device__ int   g_done[NBLK];

#define CP16(dst_s, src_g) \
    asm volatile("cp.async.cg.shared.global [%0], [%1], 16;\n" :: "r"(dst_s), "l"(src_g))
#define CP8(dst_s, src_g) \
    asm volatile("cp.async.ca.shared.global [%0], [%1], 8;\n" :: "r"(dst_s), "l"(src_g))

// ---------------------------------------------------------------------------
// Prologue: reset inter-block flags (runs each graph replay before main).
// ---------------------------------------------------------------------------
__global__ void reset_flags_kernel() {
    g_done[threadIdx.x] = 0;
}

// ---------------------------------------------------------------------------
// Fused kernel. Phase A: MLP (R12-proven math) + states-copy via
// cp.async.bulk SMEM->GMEM (thread-0-issued, async-proxy drained — zero
// per-thread LDS/STG issue load). Phase B: running-softmax pooled sections
// after acquiring neighbor block's scores (R13-proven logic).
// ---------------------------------------------------------------------------
__global__ __launch_bounds__(MLPT) void fused_kernel(
    const float* __restrict__ embeds,
    const float* __restrict__ states,
    const float* __restrict__ w1, const float* __restrict__ b1,
    const float* __restrict__ w2, const float* __restrict__ b2,
    const float* __restrict__ w3, const float* __restrict__ b3,
    float* __restrict__ out)
{
    __shared__ __align__(16) float sm[SMEM_FLOATS];
    float* As  = sm;                    // [16][KPAD]
    float* wt  = As + TMM * KPAD;       // [2][WTILE] (aliased by w2, then se)
    float* h1s = wt + 2 * WTILE;        // [16][HPAD]
    float* h2s = h1s + TMM * HPAD;      // [16][HPAD]

    const int tid = threadIdx.x;
    const int bid = blockIdx.x;
    const int t0  = bid * TMM;
    float4* out4  = (float4*)out;

    const unsigned wt_s = (unsigned)__cvta_generic_to_shared(wt);
    const unsigned sm_s = (unsigned)__cvta_generic_to_shared(sm);

    // ---- stage w1 chunk 0 ----
    for (int u = tid; u < HID * 16; u += MLPT) {
        const int j = u >> 4, seg = u & 15;
        const int rm = (j >> 1) + (j & 1) * 80;
        CP16(wt_s + (unsigned)(rm * WROW + seg * 4) * 4,
             w1 + (size_t)j * SDIM + seg * 4);
    }
    asm volatile("cp.async.commit_group;\n" ::: "memory");

    // ---- stage 16 token states ----
    for (int idx = tid; idx < TMM * (SDIM / 4); idx += MLPT) {
        const int t = idx >> 8, k4 = idx & 255;
        const float4 v = ((const float4*)states)[(size_t)(t0 + t) * 256 + k4];
        *(float4*)&As[t * KPAD + k4 * 4] = v;
    }

    const int q  = tid & 3;
    const int kh = (tid >> 2) & 1;
    const int jp = tid >> 3;
    const int j0 = 2 * jp;
    const int re = min(jp, 74);
    const int ro = 80 + re;

    const float* A0 = As + (q + 0)  * KPAD;
    const float* A1 = As + (q + 4)  * KPAD;
    const float* A2 = As + (q + 8)  * KPAD;
    const float* A3 = As + (q + 12) * KPAD;

    float e0 = 0.f, e1 = 0.f, e2 = 0.f, e3 = 0.f;
    float o0 = 0.f, o1 = 0.f, o2 = 0.f, o3 = 0.f;

    for (int c = 0; c < CHUNKS; ++c) {
        if (c + 1 < CHUNKS) {
            const int nb = (c + 1) & 1;
            for (int u = tid; u < HID * 16; u += MLPT) {
                const int j = u >> 4, seg = u & 15;
                const int rm = (j >> 1) + (j & 1) * 80;
                CP16(wt_s + (unsigned)(nb * WTILE + rm * WROW + seg * 4) * 4,
                     w1 + (size_t)j * SDIM + (c + 1) * KC + seg * 4);
            }
            asm volatile("cp.async.commit_group;\n" ::: "memory");
            asm volatile("cp.async.wait_group 1;\n" ::: "memory");
        } else {
            asm volatile("cp.async.wait_group 0;\n" ::: "memory");
        }
        __syncthreads();

        // ---- thread 0: issue 20 bulk copies (4KB each) for token th = c ----
        // (states sections of the output; async-proxy drains to GMEM without
        //  occupying warp issue slots)
        if (tid == 0) {
            asm volatile("fence.proxy.async;" ::: "memory");
            const int th = c;
            const int r  = t0 + th;
            const unsigned src = sm_s + (unsigned)(th * KPAD) * 4;
            #pragma unroll
            for (int wi = 0; wi < MAXW; wi++) {
                const int tri = wi * (T_TOK + 1) - ((wi + 1) * wi) / 2;
                if (r + wi < T_TOK) {
                    float* dst = out + (size_t)(tri + r) * 3072;
                    asm volatile(
                        "cp.async.bulk.global.shared::cta.bulk_group [%0], [%1], %2;"
                        :: "l"(dst), "r"(src), "r"(4096) : "memory");
                }
                if (r - wi >= 0) {
                    float* dst = out + (size_t)(tri + r - wi) * 3072 + 1024;
                    asm volatile(
                        "cp.async.bulk.global.shared::cta.bulk_group [%0], [%1], %2;"
                        :: "l"(dst), "r"(src), "r"(4096) : "memory");
                }
            }
            asm volatile("cp.async.bulk.commit_group;" ::: "memory");
        }

        const float* wb = wt + (c & 1) * WTILE;
        const float* we = wb + re * WROW + kh * 4;
        const float* wo = wb + ro * WROW + kh * 4;
        const float* B0 = A0 + c * KC + kh * 4;
        const float* B1 = A1 + c * KC + kh * 4;
        const float* B2 = A2 + c * KC + kh * 4;
        const float* B3 = A3 + c * KC + kh * 4;

        #pragma unroll
        for (int i = 0; i < 8; ++i) {
            const int o = i * 8;
            const float4 w_e = *(const float4*)(we + o);
            const float4 w_o = *(const float4*)(wo + o);
            const float4 a0 = *(const float4*)(B0 + o);
            const float4 a1 = *(const float4*)(B1 + o);
            const float4 a2 = *(const float4*)(B2 + o);
            const float4 a3 = *(const float4*)(B3 + o);
            e0 = fmaf(w_e.x, a0.x, e0); e0 = fmaf(w_e.y, a0.y, e0);
            e0 = fmaf(w_e.z, a0.z, e0); e0 = fmaf(w_e.w, a0.w, e0);
            e1 = fmaf(w_e.x, a1.x, e1); e1 = fmaf(w_e.y, a1.y, e1);
            e1 = fmaf(w_e.z, a1.z, e1); e1 = fmaf(w_e.w, a1.w, e1);
            e2 = fmaf(w_e.x, a2.x, e2); e2 = fmaf(w_e.y, a2.y, e2);
            e2 = fmaf(w_e.z, a2.z, e2); e2 = fmaf(w_e.w, a2.w, e2);
            e3 = fmaf(w_e.x, a3.x, e3); e3 = fmaf(w_e.y, a3.y, e3);
            e3 = fmaf(w_e.z, a3.z, e3); e3 = fmaf(w_e.w, a3.w, e3);
            o0 = fmaf(w_o.x, a0.x, o0); o0 = fmaf(w_o.y, a0.y, o0);
            o0 = fmaf(w_o.z, a0.z, o0); o0 = fmaf(w_o.w, a0.w, o0);
            o1 = fmaf(w_o.x, a1.x, o1); o1 = fmaf(w_o.y, a1.y, o1);
            o1 = fmaf(w_o.z, a1.z, o1); o1 = fmaf(w_o.w, a1.w, o1);
            o2 = fmaf(w_o.x, a2.x, o2); o2 = fmaf(w_o.y, a2.y, o2);
            o2 = fmaf(w_o.z, a2.z, o2); o2 = fmaf(w_o.w, a2.w, o2);
            o3 = fmaf(w_o.x, a3.x, o3); o3 = fmaf(w_o.y, a3.y, o3);
            o3 = fmaf(w_o.z, a3.z, o3); o3 = fmaf(w_o.w, a3.w, o3);
        }
        __syncthreads();
    }

    // ---- stage w2 ----
    for (int u = tid; u < HID * (HID / 2); u += MLPT) {
        const int j = u / (HID / 2), s2 = u - j * (HID / 2);
        const int rm = (j >> 1) + (j & 1) * 76;
        CP8(wt_s + (unsigned)(rm * W2ROW + s2 * 2) * 4,
            w2 + (size_t)j * HID + s2 * 2);
    }
    asm volatile("cp.async.commit_group;\n" ::: "memory");

    // ---- write layer-1 partials ----
    if (j0 < HID) {
        float* P = kh ? h2s : h1s;
        P[(q + 0)  * HPAD + j0]     = e0;
        P[(q + 4)  * HPAD + j0]     = e1;
        P[(q + 8)  * HPAD + j0]     = e2;
        P[(q + 12) * HPAD + j0]     = e3;
        P[(q + 0)  * HPAD + j0 + 1] = o0;
        P[(q + 4)  * HPAD + j0 + 1] = o1;
        P[(q + 8)  * HPAD + j0 + 1] = o2;
        P[(q + 12) * HPAD + j0 + 1] = o3;
    }
    __syncthreads();

    // ---- combine partials: h1 = relu(p_even + p_odd + b1) ----
    for (int idx = tid; idx < TMM * 160; idx += MLPT) {
        const int t = idx / 160, j = idx - t * 160;
        if (j < HID)
            h1s[t * HPAD + j] = fmaxf(h1s[t * HPAD + j] + h2s[t * HPAD + j]
                                      + b1[j], 0.f);
    }
    asm volatile("cp.async.wait_group 0;\n" ::: "memory");
    __syncthreads();

    // ---------------- layer 2 ----------------
    {
        const int j  = tid >> 2;
        const int jc = min(j, HID - 1);
        const int rm = (jc >> 1) + (jc & 1) * 76;
        const float* wr = wt + rm * W2ROW;
        const float* B0 = h1s + (q + 0)  * HPAD;
        const float* B1 = h1s + (q + 4)  * HPAD;
        const float* B2 = h1s + (q + 8)  * HPAD;
        const float* B3 = h1s + (q + 12) * HPAD;

        float c0 = 0.f, c1 = 0.f, c2 = 0.f, c3 = 0.f;
        #pragma unroll 5
        for (int p = 0; p < HID / 2; ++p) {
            const float2 wv = *(const float2*)(wr + 2 * p);
            const float2 a0 = *(const float2*)(B0 + 2 * p);
            const float2 a1 = *(const float2*)(B1 + 2 * p);
            const float2 a2 = *(const float2*)(B2 + 2 * p);
            const float2 a3 = *(const float2*)(B3 + 2 * p);
            c0 = fmaf(wv.x, a0.x, c0); c0 = fmaf(wv.y, a0.y, c0);
            c1 = fmaf(wv.x, a1.x, c1); c1 = fmaf(wv.y, a1.y, c1);
            c2 = fmaf(wv.x, a2.x, c2); c2 = fmaf(wv.y, a2.y, c2);
            c3 = fmaf(wv.x, a3.x, c3); c3 = fmaf(wv.y, a3.y, c3);
        }
        __syncthreads();
        if (j < HID) {
            const float bb = b2[j];
            h2s[(q + 0)  * HPAD + j] = fmaxf(c0 + bb, 0.f);
            h2s[(q + 4)  * HPAD + j] = fmaxf(c1 + bb, 0.f);
            h2s[(q + 8)  * HPAD + j] = fmaxf(c2 + bb, 0.f);
            h2s[(q + 12) * HPAD + j] = fmaxf(c3 + bb, 0.f);
        }
    }
    __syncthreads();

    // ---- drain bulk stores before reusing the As region for phase B ----
    if (tid == 0) {
        asm volatile("cp.async.bulk.wait_group.read 0;" ::: "memory");
    }
    __syncthreads();

    // ---- phase-B embed prefetch (As/wt regions now dead except h2s) ----
    {
        const int nrows = min(TMM + MAXW - 1, T_TOK - t0);   // up to 25
        const int f4 = tid & 255, rr = tid >> 8;
        for (int i = rr; i < nrows; i += 2) {
            if (tid < 512)
                CP16(sm_s + (unsigned)(SE_OFF + i * EDIM + f4 * 4) * 4,
                     (const float4*)embeds + (size_t)(t0 + i) * 256 + f4);
        }
        asm volatile("cp.async.commit_group;\n" ::: "memory");
    }

    // ---------------- layer 3 + score publish ----------------
    {
        const int wrp  = tid >> 5;
        const int lane = tid & 31;
        if (wrp < TMM) {
            float acc = 0.f;
            #pragma unroll
            for (int i = 0; i < 5; ++i) {
                const int kk = lane + 32 * i;
                if (kk < HID) acc += w3[kk] * h2s[wrp * HPAD + kk];
            }
            #pragma unroll
            for (int off = 16; off; off >>= 1)
                acc += __shfl_xor_sync(0xffffffffu, acc, off);
            if (lane == 0) {
                const float v = acc + b3[0];
                g_attns[t0 + wrp] = v;
                sm[SCB_OFF + wrp] = v;        // own scores to smem
            }
        }
    }
    __threadfence();
    __syncthreads();
    if (tid == 0) atomicExch(&g_done[bid], 1);

    // ---- acquire neighbor's scores ----
    if (tid == 0 && bid + 1 < NBLK) {
        while (atomicAdd(&g_done[bid + 1], 0) == 0) { }
    }
    __threadfence();
    __syncthreads();

    if (tid < MAXW - 1 && t0 + TMM + tid < T_TOK)
        sm[SCB_OFF + TMM + tid] = g_attns[t0 + TMM + tid];
    __syncthreads();

    // ---- softmax prefixes for 16 starts ----
    if (tid < TMM) {
        const int r  = t0 + tid;
        const int nm = min(MAXW, T_TOK - r);
        float m = -1e30f;
        for (int i = 0; i < nm; i++) m = fmaxf(m, sm[SCB_OFF + tid + i]);
        float den = 0.f;
        for (int i = 0; i < nm; i++) {
            const float e = __expf(sm[SCB_OFF + tid + i] - m);
            sm[WS_OFF + tid * MAXW + i] = e;
            den += e;
            sm[IDN_OFF + tid * MAXW + i] = 1.0f / den;
        }
    }
    asm volatile("cp.async.wait_group 0;\n" ::: "memory");
    __syncthreads();

    // ---- pooled compute + stores: 512 threads, 8 starts per group ---------
    if (tid < 512) {
        const int grp = tid >> 8;          // 0..1
        const int f4  = tid & 255;
        #pragma unroll
        for (int rr8 = 0; rr8 < 8; rr8++) {
            const int rr = grp * 8 + rr8;
            const int r  = t0 + rr;
            const int nm = min(MAXW, T_TOK - r);
            float4 num = make_float4(0.f, 0.f, 0.f, 0.f);
            #pragma unroll
            for (int i = 0; i < MAXW; i++) {
                if (i < nm) {
                    const float  wv = sm[WS_OFF + rr * MAXW + i];
                    const float4 e  =
                        *(const float4*)&sm[SE_OFF + (rr + i) * EDIM + f4 * 4];
                    num.x += wv * e.x; num.y += wv * e.y;
                    num.z += wv * e.z; num.w += wv * e.w;

                    const int row = i * (T_TOK + 1) - ((i + 1) * i) / 2 + r;
                    const float id = sm[IDN_OFF + rr * MAXW + i];
                    __stcs(&out4[row * 768 + 512 + f4],
                           make_float4(num.x * id, num.y * id,
                                       num.z * id, num.w * id));
                }
            }
        }
    }
}

// ---------------------------------------------------------------------------
extern "C" void kernel_launch(void* const* d_in, const int* in_sizes, int n_in,
                              void* d_out, int out_size) {
    const float* embeds = (const float*)d_in[0];
    const float* states = (const float*)d_in[1];
    const float* w1     = (const float*)d_in[2];
    const float* b1     = (const float*)d_in[3];
    const float* w2     = (const float*)d_in[4];
    const float* b2     = (const float*)d_in[5];
    const float* w3     = (const float*)d_in[6];
    const float* b3     = (const float*)d_in[7];
    float* out = (float*)d_out;

    reset_flags_kernel<<<1, NBLK>>>();
    fused_kernel<<<NBLK, MLPT>>>(embeds, states, w1, b1, w2, b2, w3, b3, out);
}

// round 17
// speedup vs baseline: 1.2289x; 1.0016x over previous
#include <cuda_runtime.h>

#define T_TOK 2048
#define SDIM  1024
#define EDIM  1024
#define HID   150
#define MAXW  10

#define TMM    16             // tokens per block
#define MLPT   640            // threads (20 warps = 5/SMSP)
#define KPAD   1032           // As row stride (floats)
#define HPAD   158            // h row stride (floats)
#define WROW   88             // w1 tile row stride (floats)
#define KC     64             // K-chunk (floats)
#define CHUNKS 16             // 1024 / 64
#define WTILE  (160 * WROW)   // floats per w1 buffer (14080)
#define NBLK   (T_TOK / TMM)  // 128 blocks (all co-resident: 1/SM)

#define SMEM_FLOATS (TMM*KPAD + 2*WTILE + 2*TMM*HPAD)   // 49728 -> ~199 KB

// phase-B smem carve-out (aliases As+wt, free after layer 2):
#define SE_OFF   0          // 25 embed rows x 1024 floats = 25600
#define SCB_OFF  25600      // 25 scores
#define WS_OFF   25632      // 16 starts x 10 widths
#define IDN_OFF  25792      // 16 x 10

#define W1_TX    (HID * KC * 4)      // 38400 B per w1 chunk
#define W2_TX    (HID * HID * 4)     // 90000 B

__device__ float g_attns[T_TOK];
__device__ int   g_done[NBLK];      // consume-and-reset; zero-initialized

// ---- mbarrier helpers ----
#define MB_INIT(a, n) \
    asm volatile("mbarrier.init.shared.b64 [%0], %1;" :: "r"(a), "r"(n) : "memory")
#define MB_EXPECT(a, tx) \
    asm volatile("mbarrier.arrive.expect_tx.shared.b64 _, [%0], %1;" \
                 :: "r"(a), "r"(tx) : "memory")
#define MB_WAIT(a, par) do {                                             \
    unsigned _done;                                                      \
    asm volatile("{\n\t.reg .pred p;\n\t"                                \
        "mbarrier.try_wait.parity.acquire.cta.shared::cta.b64 p, [%1], %2;\n\t" \
        "selp.b32 %0, 1, 0, p;\n\t}"                                     \
        : "=r"(_done) : "r"(a), "r"(par) : "memory");                    \
    while (!_done) {                                                     \
        asm volatile("{\n\t.reg .pred p;\n\t"                            \
            "mbarrier.try_wait.parity.acquire.cta.shared::cta.b64 p, [%1], %2, 0x989680;\n\t" \
            "selp.b32 %0, 1, 0, p;\n\t}"                                 \
            : "=r"(_done) : "r"(a), "r"(par) : "memory");                \
    }                                                                    \
} while (0)

#define BULK_G2S(dst_s, src_g, bytes, mbar_s) \
    asm volatile("cp.async.bulk.shared::cluster.global.mbarrier::complete_tx::bytes " \
                 "[%0], [%1], %2, [%3];" \
                 :: "r"(dst_s), "l"(src_g), "r"(bytes), "r"(mbar_s) : "memory")
#define BULK_S2G(dst_g, src_s, bytes) \
    asm volatile("cp.async.bulk.global.shared::cta.bulk_group [%0], [%1], %2;" \
                 :: "l"(dst_g), "r"(src_s), "r"(bytes) : "memory")

// ---------------------------------------------------------------------------
// Fused kernel. Phase A: MLP (proven math) + states-copy via bulk S->G.
// ALL weight/embed staging via cp.async.bulk (UBLKCP) + mbarrier: ~170 async
// issues per chunk from 6 lanes instead of 2400 warp-wide cp.asyncs.
// Phase B: running-softmax pooled sections after neighbor-score handshake
// (consume-and-reset flags, no prologue kernel).
// ---------------------------------------------------------------------------
__global__ __launch_bounds__(MLPT) void fused_kernel(
    const float* __restrict__ embeds,
    const float* __restrict__ states,
    const float* __restrict__ w1, const float* __restrict__ b1,
    const float* __restrict__ w2, const float* __restrict__ b2,
    const float* __restrict__ w3, const float* __restrict__ b3,
    float* __restrict__ out)
{
    __shared__ __align__(16) float sm[SMEM_FLOATS];
    __shared__ __align__(16) unsigned long long mbars[3];  // w1 buf0, buf1, misc

    float* As  = sm;                    // [16][KPAD]
    float* wt  = As + TMM * KPAD;       // [2][WTILE] (aliased by w2, then se)
    float* h1s = wt + 2 * WTILE;        // [16][HPAD]
    float* h2s = h1s + TMM * HPAD;      // [16][HPAD]

    const int tid = threadIdx.x;
    const int bid = blockIdx.x;
    const int t0  = bid * TMM;
    float4* out4  = (float4*)out;

    const unsigned sm_s = (unsigned)__cvta_generic_to_shared(sm);
    const unsigned wt_s = sm_s + (unsigned)(TMM * KPAD) * 4;
    const unsigned mb_s = (unsigned)__cvta_generic_to_shared(mbars);

    if (tid == 0) {
        MB_INIT(mb_s + 0, 1);
        MB_INIT(mb_s + 8, 1);
        MB_INIT(mb_s + 16, 1);
    }
    __syncthreads();

    // ---- stage w1 chunk 0 via bulk (5 issuer lanes x 30 rows) ----
    if (tid == 0) MB_EXPECT(mb_s + 0, W1_TX);
    if ((tid & 31) == 0 && tid < 160) {
        const int wi = tid >> 5;
        for (int j = wi; j < HID; j += 5) {
            const int rm = (j >> 1) + (j & 1) * 80;
            BULK_G2S(wt_s + (unsigned)(rm * WROW) * 4,
                     w1 + (size_t)j * SDIM, 256, mb_s + 0);
        }
    }

    // ---- stage 16 token states (plain LDG->STS) ----
    for (int idx = tid; idx < TMM * (SDIM / 4); idx += MLPT) {
        const int t = idx >> 8, k4 = idx & 255;
        const float4 v = ((const float4*)states)[(size_t)(t0 + t) * 256 + k4];
        *(float4*)&As[t * KPAD + k4 * 4] = v;
    }
    __syncthreads();            // As visible to all before compute

    const int q  = tid & 3;
    const int kh = (tid >> 2) & 1;
    const int jp = tid >> 3;
    const int j0 = 2 * jp;
    const int re = min(jp, 74);
    const int ro = 80 + re;

    const float* A0 = As + (q + 0)  * KPAD;
    const float* A1 = As + (q + 4)  * KPAD;
    const float* A2 = As + (q + 8)  * KPAD;
    const float* A3 = As + (q + 12) * KPAD;

    float e0 = 0.f, e1 = 0.f, e2 = 0.f, e3 = 0.f;
    float o0 = 0.f, o1 = 0.f, o2 = 0.f, o3 = 0.f;
    int ph0 = 0, ph1 = 0;

    for (int c = 0; c < CHUNKS; ++c) {
        // ---- issue chunk c+1 into the other buffer ----
        if (c + 1 < CHUNKS) {
            const int nb = (c + 1) & 1;
            if (tid == 0) MB_EXPECT(mb_s + nb * 8, W1_TX);
            if ((tid & 31) == 0 && tid < 160) {
                const int wi = tid >> 5;
                for (int j = wi; j < HID; j += 5) {
                    const int rm = (j >> 1) + (j & 1) * 80;
                    BULK_G2S(wt_s + (unsigned)(nb * WTILE + rm * WROW) * 4,
                             w1 + (size_t)j * SDIM + (c + 1) * KC, 256,
                             mb_s + nb * 8);
                }
            }
        }

        // ---- states-section bulk stores for token th = c (warp 5 lane 0) ----
        if (tid == 160) {
            asm volatile("fence.proxy.async;" ::: "memory");
            const int th = c;
            const int r  = t0 + th;
            const unsigned src = sm_s + (unsigned)(th * KPAD) * 4;
            #pragma unroll
            for (int wi = 0; wi < MAXW; wi++) {
                const int tri = wi * (T_TOK + 1) - ((wi + 1) * wi) / 2;
                if (r + wi < T_TOK)
                    BULK_S2G(out + (size_t)(tri + r) * 3072, src, 4096);
                if (r - wi >= 0)
                    BULK_S2G(out + (size_t)(tri + r - wi) * 3072 + 1024, src, 4096);
            }
            asm volatile("cp.async.bulk.commit_group;" ::: "memory");
        }

        // ---- wait for this chunk's w1 buffer ----
        if ((c & 1) == 0) { MB_WAIT(mb_s + 0, (ph0 & 1)); ph0++; }
        else             { MB_WAIT(mb_s + 8, (ph1 & 1)); ph1++; }

        const float* wb = wt + (c & 1) * WTILE;
        const float* we = wb + re * WROW + kh * 4;
        const float* wo = wb + ro * WROW + kh * 4;
        const float* B0 = A0 + c * KC + kh * 4;
        const float* B1 = A1 + c * KC + kh * 4;
        const float* B2 = A2 + c * KC + kh * 4;
        const float* B3 = A3 + c * KC + kh * 4;

        #pragma unroll
        for (int i = 0; i < 8; ++i) {
            const int o = i * 8;
            const float4 w_e = *(const float4*)(we + o);
            const float4 w_o = *(const float4*)(wo + o);
            const float4 a0 = *(const float4*)(B0 + o);
            const float4 a1 = *(const float4*)(B1 + o);
            const float4 a2 = *(const float4*)(B2 + o);
            const float4 a3 = *(const float4*)(B3 + o);
            e0 = fmaf(w_e.x, a0.x, e0); e0 = fmaf(w_e.y, a0.y, e0);
            e0 = fmaf(w_e.z, a0.z, e0); e0 = fmaf(w_e.w, a0.w, e0);
            e1 = fmaf(w_e.x, a1.x, e1); e1 = fmaf(w_e.y, a1.y, e1);
            e1 = fmaf(w_e.z, a1.z, e1); e1 = fmaf(w_e.w, a1.w, e1);
            e2 = fmaf(w_e.x, a2.x, e2); e2 = fmaf(w_e.y, a2.y, e2);
            e2 = fmaf(w_e.z, a2.z, e2); e2 = fmaf(w_e.w, a2.w, e2);
            e3 = fmaf(w_e.x, a3.x, e3); e3 = fmaf(w_e.y, a3.y, e3);
            e3 = fmaf(w_e.z, a3.z, e3); e3 = fmaf(w_e.w, a3.w, e3);
            o0 = fmaf(w_o.x, a0.x, o0); o0 = fmaf(w_o.y, a0.y, o0);
            o0 = fmaf(w_o.z, a0.z, o0); o0 = fmaf(w_o.w, a0.w, o0);
            o1 = fmaf(w_o.x, a1.x, o1); o1 = fmaf(w_o.y, a1.y, o1);
            o1 = fmaf(w_o.z, a1.z, o1); o1 = fmaf(w_o.w, a1.w, o1);
            o2 = fmaf(w_o.x, a2.x, o2); o2 = fmaf(w_o.y, a2.y, o2);
            o2 = fmaf(w_o.z, a2.z, o2); o2 = fmaf(w_o.w, a2.w, o2);
            o3 = fmaf(w_o.x, a3.x, o3); o3 = fmaf(w_o.y, a3.y, o3);
            o3 = fmaf(w_o.z, a3.z, o3); o3 = fmaf(w_o.w, a3.w, o3);
        }
        __syncthreads();   // all reads of this buffer done before it is re-staged
    }

    // ---- stage w2: ONE 90KB bulk into unpadded tile at wt ----
    if (tid == 0) {
        asm volatile("fence.proxy.async;" ::: "memory");
        MB_EXPECT(mb_s + 16, W2_TX);
        BULK_G2S(wt_s, w2, W2_TX, mb_s + 16);
    }

    // ---- write layer-1 partials ----
    if (j0 < HID) {
        float* P = kh ? h2s : h1s;
        P[(q + 0)  * HPAD + j0]     = e0;
        P[(q + 4)  * HPAD + j0]     = e1;
        P[(q + 8)  * HPAD + j0]     = e2;
        P[(q + 12) * HPAD + j0]     = e3;
        P[(q + 0)  * HPAD + j0 + 1] = o0;
        P[(q + 4)  * HPAD + j0 + 1] = o1;
        P[(q + 8)  * HPAD + j0 + 1] = o2;
        P[(q + 12) * HPAD + j0 + 1] = o3;
    }
    __syncthreads();

    // ---- combine partials: h1 = relu(p_even + p_odd + b1) ----
    for (int idx = tid; idx < TMM * 160; idx += MLPT) {
        const int t = idx / 160, j = idx - t * 160;
        if (j < HID)
            h1s[t * HPAD + j] = fmaxf(h1s[t * HPAD + j] + h2s[t * HPAD + j]
                                      + b1[j], 0.f);
    }
    MB_WAIT(mb_s + 16, 0);      // w2 tile ready (phase 0)
    __syncthreads();

    // ---------------- layer 2 (unpadded w2 rows: stride HID) ---------------
    {
        const int j  = tid >> 2;
        const int jc = min(j, HID - 1);
        const float* wr = wt + jc * HID;
        const float* B0 = h1s + (q + 0)  * HPAD;
        const float* B1 = h1s + (q + 4)  * HPAD;
        const float* B2 = h1s + (q + 8)  * HPAD;
        const float* B3 = h1s + (q + 12) * HPAD;

        float c0 = 0.f, c1 = 0.f, c2 = 0.f, c3 = 0.f;
        #pragma unroll 5
        for (int p = 0; p < HID / 2; ++p) {
            const float2 wv = *(const float2*)(wr + 2 * p);
            const float2 a0 = *(const float2*)(B0 + 2 * p);
            const float2 a1 = *(const float2*)(B1 + 2 * p);
            const float2 a2 = *(const float2*)(B2 + 2 * p);
            const float2 a3 = *(const float2*)(B3 + 2 * p);
            c0 = fmaf(wv.x, a0.x, c0); c0 = fmaf(wv.y, a0.y, c0);
            c1 = fmaf(wv.x, a1.x, c1); c1 = fmaf(wv.y, a1.y, c1);
            c2 = fmaf(wv.x, a2.x, c2); c2 = fmaf(wv.y, a2.y, c2);
            c3 = fmaf(wv.x, a3.x, c3); c3 = fmaf(wv.y, a3.y, c3);
        }
        __syncthreads();
        if (j < HID) {
            const float bb = b2[j];
            h2s[(q + 0)  * HPAD + j] = fmaxf(c0 + bb, 0.f);
            h2s[(q + 4)  * HPAD + j] = fmaxf(c1 + bb, 0.f);
            h2s[(q + 8)  * HPAD + j] = fmaxf(c2 + bb, 0.f);
            h2s[(q + 12) * HPAD + j] = fmaxf(c3 + bb, 0.f);
        }
    }
    __syncthreads();

    // ---- drain states-section bulk stores (frees As region) ----
    if (tid == 0)
        asm volatile("cp.async.bulk.wait_group.read 0;" ::: "memory");
    __syncthreads();

    // ---- phase-B embed prefetch: nrows bulk row-copies (mb2 phase 1) ----
    const int nrows = min(TMM + MAXW - 1, T_TOK - t0);   // up to 25
    if (tid == 0) MB_EXPECT(mb_s + 16, (unsigned)(nrows * 4096));
    if ((tid & 31) == 0 && tid < 160) {
        asm volatile("fence.proxy.async;" ::: "memory");
        const int wi = tid >> 5;
        for (int i = wi; i < nrows; i += 5) {
            BULK_G2S(sm_s + (unsigned)(SE_OFF + i * EDIM) * 4,
                     embeds + (size_t)(t0 + i) * EDIM, 4096, mb_s + 16);
        }
    }

    // ---------------- layer 3 + score publish ----------------
    {
        const int wrp  = tid >> 5;
        const int lane = tid & 31;
        if (wrp < TMM) {
            float acc = 0.f;
            #pragma unroll
            for (int i = 0; i < 5; ++i) {
                const int kk = lane + 32 * i;
                if (kk < HID) acc += w3[kk] * h2s[wrp * HPAD + kk];
            }
            #pragma unroll
            for (int off = 16; off; off >>= 1)
                acc += __shfl_xor_sync(0xffffffffu, acc, off);
            if (lane == 0) {
                const float v = acc + b3[0];
                g_attns[t0 + wrp] = v;
                sm[SCB_OFF + wrp] = v;
            }
        }
    }
    __threadfence();
    __syncthreads();
    if (tid == 0) atomicExch(&g_done[bid], 1);

    // ---- acquire neighbor's scores, then consume-and-reset its flag ----
    if (tid == 0 && bid + 1 < NBLK) {
        while (atomicAdd(&g_done[bid + 1], 0) == 0) { }
    }
    __threadfence();
    __syncthreads();

    if (tid < MAXW - 1 && t0 + TMM + tid < T_TOK)
        sm[SCB_OFF + TMM + tid] = g_attns[t0 + TMM + tid];
    __syncthreads();
    if (tid == 0 && bid + 1 < NBLK) atomicExch(&g_done[bid + 1], 0);

    // ---- softmax prefixes for 16 starts ----
    if (tid < TMM) {
        const int r  = t0 + tid;
        const int nm = min(MAXW, T_TOK - r);
        float m = -1e30f;
        for (int i = 0; i < nm; i++) m = fmaxf(m, sm[SCB_OFF + tid + i]);
        float den = 0.f;
        for (int i = 0; i < nm; i++) {
            const float e = __expf(sm[SCB_OFF + tid + i] - m);
            sm[WS_OFF + tid * MAXW + i] = e;
            den += e;
            sm[IDN_OFF + tid * MAXW + i] = 1.0f / den;
        }
    }
    MB_WAIT(mb_s + 16, 1);      // embed rows ready (phase 1)
    __syncthreads();

    // ---- pooled compute + stores: 512 threads, 8 starts per group ---------
    if (tid < 512) {
        const int grp = tid >> 8;          // 0..1
        const int f4  = tid & 255;
        #pragma unroll
        for (int rr8 = 0; rr8 < 8; rr8++) {
            const int rr = grp * 8 + rr8;
            const int r  = t0 + rr;
            const int nm = min(MAXW, T_TOK - r);
            float4 num = make_float4(0.f, 0.f, 0.f, 0.f);
            #pragma unroll
            for (int i = 0; i < MAXW; i++) {
                if (i < nm) {
                    const float  wv = sm[WS_OFF + rr * MAXW + i];
                    const float4 e  =
                        *(const float4*)&sm[SE_OFF + (rr + i) * EDIM + f4 * 4];
                    num.x += wv * e.x; num.y += wv * e.y;
                    num.z += wv * e.z; num.w += wv * e.w;

                    const int row = i * (T_TOK + 1) - ((i + 1) * i) / 2 + r;
                    const float id = sm[IDN_OFF + rr * MAXW + i];
                    __stcs(&out4[row * 768 + 512 + f4],
                           make_float4(num.x * id, num.y * id,
                                       num.z * id, num.w * id));
                }
            }
        }
    }
}

// ---------------------------------------------------------------------------
extern "C" void kernel_launch(void* const* d_in, const int* in_sizes, int n_in,
                              void* d_out, int out_size) {
    const float* embeds = (const float*)d_in[0];
    const float* states = (const float*)d_in[1];
    const float* w1     = (const float*)d_in[2];
    const float* b1     = (const float*)d_in[3];
    const float* w2     = (const float*)d_in[4];
    const float* b2     = (const float*)d_in[5];
    const float* w3     = (const float*)d_in[6];
    const float* b3     = (const float*)d_in[7];
    float* out = (float*)d_out;

    fused_kernel<<<NBLK, MLPT>>>(embeds, states, w1, b1, w2, b2, w3, b3, out);
}